// round 2
// baseline (speedup 1.0000x reference)
#include <cuda_runtime.h>
#include <math.h>

// CWT gaus1, scales {1,3,6}, x:(32,4096,64) f32 -> out:(32,3,4096,64) f32.
//
// Folded form: out_a[b,s,c] = sum_m h_a[m] * x[b, s + start_a + m, c]
//   h_a[m] = -sqrt(a)*(f_a[m-1]-f_a[m]),  f_a[i] = int_psi[floor(i/(a*step))]
// Unified window p in [0,61] relative to x[s-31]: scale6 tap m=p (all p),
// scale3 m=p-15 for p in [15,46], scale1 m=p-25 for p in [25,36].
//
// int_psi replicated via Euler-Maclaurin (error ~1e-8 vs numpy cumsum).
//
// R2: 4 seq pos x 2 channels per thread (12 ULL accum, 4 ULL window) to cut
// regs ~95 -> ~50 and raise occupancy 2 -> 4-5 blocks/SM.

#define S_LEN 4096
#define C_LEN 64
#define TILE_S 32
#define NROWS 93   // TILE_S + 61

__device__ __forceinline__ void ffma2(unsigned long long &d,
                                      unsigned long long a,
                                      unsigned long long b) {
    asm("fma.rn.f32x2 %0, %1, %2, %0;" : "+l"(d) : "l"(a), "l"(b));
}

__device__ __forceinline__ double ipsi_em(long j) {
    const double step = 10.0 / 1023.0;
    double u = (j >= 1023) ? 5.0 : ((double)j * step + (-5.0));
    double e = exp(-u * u);
    double v = e * (1.0 - step * u + (step * step / 12.0) * (4.0 * u * u - 2.0));
    return v / sqrt(sqrt(M_PI / 2.0));   // (pi/2)^(1/4)
}

// f_a[i] as float (numpy casts int_psi[j] to float32); zero outside [0,L)
__device__ __forceinline__ float f_at(int a, int i, int L) {
    if (i < 0 || i >= L) return 0.0f;
    const double step = 10.0 / 1023.0;
    double as_ = (double)a * step;          // matches numpy a*step (f64)
    long j = (long)((double)i / as_);       // matches arange/(a*step) astype(int64)
    return (float)ipsi_em(j);
}

__global__ void __launch_bounds__(256, 4)
cwt_kernel(const float* __restrict__ x, float* __restrict__ out) {
    __shared__ float xs[NROWS][C_LEN];
    __shared__ unsigned long long g6s[62], g3s[32], g1s[12];

    const int tid  = threadIdx.x;
    const int b    = blockIdx.y;
    const int s0   = blockIdx.x * TILE_S;

    // ---- fill smem tile (rows s0-31 .. s0+61, zero-padded at edges) ----
    const float4* xg = (const float4*)x + (size_t)b * (S_LEN * (C_LEN / 4));
    const float4 z4 = make_float4(0.f, 0.f, 0.f, 0.f);
    #pragma unroll
    for (int k = 0; k < 6; k++) {
        int f = tid + k * 256;
        if (f < NROWS * 16) {
            int row = f >> 4, q = f & 15;
            int gs = s0 - 31 + row;
            float4 v = (gs >= 0 && gs < S_LEN) ? xg[gs * 16 + q] : z4;
            *(float4*)&xs[row][q * 4] = v;
        }
    }

    // ---- per-block coefficient computation (106 taps) ----
    if (tid < 106) {
        int a, m, L;
        unsigned long long* dst;
        if (tid < 62)       { a = 6; L = 61; m = tid;      dst = &g6s[m]; }
        else if (tid < 94)  { a = 3; L = 31; m = tid - 62; dst = &g3s[m]; }
        else                { a = 1; L = 11; m = tid - 94; dst = &g1s[m]; }
        float h = -(float)sqrt((double)a) * (f_at(a, m - 1, L) - f_at(a, m, L));
        unsigned int bits = __float_as_uint(h);
        *dst = ((unsigned long long)bits << 32) | (unsigned long long)bits;
    }
    __syncthreads();

    // ---- compute: thread = 2 channels x 4 seq positions x 3 scales ----
    const int ch2   = tid & 31;     // channel pair index (2 channels)
    const int sg    = tid >> 5;     // 0..7 seq group
    const int rbase = sg * 4;

    unsigned long long win[4];
    #pragma unroll
    for (int i = 0; i < 4; i++)
        win[i] = *(const unsigned long long*)&xs[rbase + i][ch2 * 2];

    unsigned long long a6[4] = {0,0,0,0};
    unsigned long long a3[4] = {0,0,0,0};
    unsigned long long a1[4] = {0,0,0,0};

    #pragma unroll
    for (int p = 0; p < 62; p++) {
        unsigned long long c6 = g6s[p];
        #pragma unroll
        for (int t = 0; t < 4; t++)
            ffma2(a6[t], win[(p + t) & 3], c6);
        if (p >= 15 && p < 47) {
            unsigned long long c3 = g3s[p - 15];
            #pragma unroll
            for (int t = 0; t < 4; t++)
                ffma2(a3[t], win[(p + t) & 3], c3);
        }
        if (p >= 25 && p < 37) {
            unsigned long long c1 = g1s[p - 25];
            #pragma unroll
            for (int t = 0; t < 4; t++)
                ffma2(a1[t], win[(p + t) & 3], c1);
        }
        if (p < 61)   // slide window: load row rbase+p+4 over row rbase+p
            win[p & 3] = *(const unsigned long long*)&xs[rbase + p + 4][ch2 * 2];
    }

    // ---- store: out[b, scale, s, c], scale order (1,3,6) ----
    unsigned long long* og = (unsigned long long*)out;
    const size_t ob = (size_t)b * 3 * S_LEN * 32;   // in 8B units
    const int srow = s0 + rbase;
    #pragma unroll
    for (int t = 0; t < 4; t++) {
        size_t r = (size_t)(srow + t) * 32 + ch2;
        og[ob + 0 * (size_t)S_LEN * 32 + r] = a1[t];
        og[ob + 1 * (size_t)S_LEN * 32 + r] = a3[t];
        og[ob + 2 * (size_t)S_LEN * 32 + r] = a6[t];
    }
}

extern "C" void kernel_launch(void* const* d_in, const int* in_sizes, int n_in,
                              void* d_out, int out_size) {
    const float* x = (const float*)d_in[0];
    float* out = (float*)d_out;
    dim3 grid(S_LEN / TILE_S, 32);   // (128 seq tiles, 32 batches)
    cwt_kernel<<<grid, 256>>>(x, out);
}

// round 3
// speedup vs baseline: 1.3661x; 1.3661x over previous
#include <cuda_runtime.h>
#include <math.h>

// CWT gaus1, scales {1,3,6}, x:(32,4096,64) f32 -> out:(32,3,4096,64) f32.
//
// Folded form: out_a[b,s,c] = sum_m h_a[m] * x[b, s + start_a + m, c]
//   h_a[m] = -sqrt(a)*(f_a[m-1]-f_a[m]),  f_a[i] = int_psi[floor(i/(a*step))]
// Unified window p in [0,61] relative to x[s-31]: scale6 tap m=p (all p),
// scale3 m=p-15 for p in [15,46], scale1 m=p-25 for p in [25,36].
//
// int_psi replicated via Euler-Maclaurin (error ~1e-8 vs numpy cumsum).
//
// R3: explicit software pipeline — p processed in groups of 4; rows for the
// NEXT group prefetched into a 12-deep modular register ring at group start.
// Load->use distance ~1 group (>= 27 FFMA2 slots) >> LDS latency (29 cy).

#define S_LEN 4096
#define C_LEN 64
#define TILE_S 64
#define NROWS 125   // TILE_S + 61
#define NT 512

__device__ __forceinline__ void ffma2(unsigned long long &d,
                                      unsigned long long a,
                                      unsigned long long b) {
    asm("fma.rn.f32x2 %0, %1, %2, %0;" : "+l"(d) : "l"(a), "l"(b));
}

__device__ __forceinline__ double ipsi_em(long j) {
    const double step = 10.0 / 1023.0;
    double u = (j >= 1023) ? 5.0 : ((double)j * step + (-5.0));
    double e = exp(-u * u);
    double v = e * (1.0 - step * u + (step * step / 12.0) * (4.0 * u * u - 2.0));
    return v / sqrt(sqrt(M_PI / 2.0));   // (pi/2)^(1/4)
}

// f_a[i] as float (numpy casts int_psi[j] to float32); zero outside [0,L)
__device__ __forceinline__ float f_at(int a, int i, int L) {
    if (i < 0 || i >= L) return 0.0f;
    const double step = 10.0 / 1023.0;
    double as_ = (double)a * step;          // matches numpy a*step (f64)
    long j = (long)((double)i / as_);       // matches arange/(a*step) astype(int64)
    return (float)ipsi_em(j);
}

__global__ void __launch_bounds__(NT, 2)
cwt_kernel(const float* __restrict__ x, float* __restrict__ out) {
    __shared__ float xs[NROWS][C_LEN];
    __shared__ unsigned long long g6s[62], g3s[32], g1s[12];

    const int tid = threadIdx.x;
    const int b   = blockIdx.y;
    const int s0  = blockIdx.x * TILE_S;

    // ---- fill smem tile (rows s0-31 .. s0+93, zero-padded at edges) ----
    const float4* xg = (const float4*)x + (size_t)b * (S_LEN * (C_LEN / 4));
    const float4 z4 = make_float4(0.f, 0.f, 0.f, 0.f);
    #pragma unroll
    for (int k = 0; k < 4; k++) {
        int f = tid + k * NT;
        if (f < NROWS * 16) {
            int row = f >> 4, q = f & 15;
            int gs = s0 - 31 + row;
            float4 v = (gs >= 0 && gs < S_LEN) ? xg[gs * 16 + q] : z4;
            *(float4*)&xs[row][q * 4] = v;
        }
    }

    // ---- per-block coefficient computation (106 taps) ----
    if (tid < 106) {
        int a, m, L;
        unsigned long long* dst;
        if (tid < 62)       { a = 6; L = 61; m = tid;      dst = &g6s[m]; }
        else if (tid < 94)  { a = 3; L = 31; m = tid - 62; dst = &g3s[m]; }
        else                { a = 1; L = 11; m = tid - 94; dst = &g1s[m]; }
        float h = -(float)sqrt((double)a) * (f_at(a, m - 1, L) - f_at(a, m, L));
        unsigned int bits = __float_as_uint(h);
        *dst = ((unsigned long long)bits << 32) | (unsigned long long)bits;
    }
    __syncthreads();

    // ---- compute: warp = 32 channel-pairs, thread = 4 seq pos x 3 scales ----
    const int ch2   = tid & 31;     // channel pair (lane)
    const int sg    = tid >> 5;     // warp 0..15 -> seq group
    const int rbase = sg * 4;

    // 12-deep modular register ring of rows; row r lives in buf[r % 12].
    unsigned long long buf[12];
    #pragma unroll
    for (int r = 0; r < 7; r++)
        buf[r] = *(const unsigned long long*)&xs[rbase + r][ch2 * 2];

    unsigned long long a6[4] = {0,0,0,0};
    unsigned long long a3[4] = {0,0,0,0};
    unsigned long long a1[4] = {0,0,0,0};

    #pragma unroll
    for (int g = 0; g < 16; g++) {
        // prefetch rows 4g+7 .. 4g+10 (needed by group g+1)
        #pragma unroll
        for (int i = 0; i < 4; i++) {
            int r = 4 * g + 7 + i;
            if (r <= 64)
                buf[r % 12] = *(const unsigned long long*)&xs[rbase + r][ch2 * 2];
        }
        // compute group g: p = 4g .. 4g+3, uses rows 4g .. 4g+6 (prefetched)
        #pragma unroll
        for (int pp = 0; pp < 4; pp++) {
            int p = 4 * g + pp;
            if (p < 62) {
                unsigned long long c6 = g6s[p];
                #pragma unroll
                for (int t = 0; t < 4; t++)
                    ffma2(a6[t], buf[(p + t) % 12], c6);
                if (p >= 15 && p < 47) {
                    unsigned long long c3 = g3s[p - 15];
                    #pragma unroll
                    for (int t = 0; t < 4; t++)
                        ffma2(a3[t], buf[(p + t) % 12], c3);
                }
                if (p >= 25 && p < 37) {
                    unsigned long long c1 = g1s[p - 25];
                    #pragma unroll
                    for (int t = 0; t < 4; t++)
                        ffma2(a1[t], buf[(p + t) % 12], c1);
                }
            }
        }
    }

    // ---- store: out[b, scale, s, c], scale order (1,3,6) ----
    unsigned long long* og = (unsigned long long*)out;
    const size_t ob = (size_t)b * 3 * S_LEN * 32;   // in 8B units
    const int srow = s0 + rbase;
    #pragma unroll
    for (int t = 0; t < 4; t++) {
        size_t r = (size_t)(srow + t) * 32 + ch2;
        og[ob + 0 * (size_t)S_LEN * 32 + r] = a1[t];
        og[ob + 1 * (size_t)S_LEN * 32 + r] = a3[t];
        og[ob + 2 * (size_t)S_LEN * 32 + r] = a6[t];
    }
}

extern "C" void kernel_launch(void* const* d_in, const int* in_sizes, int n_in,
                              void* d_out, int out_size) {
    const float* x = (const float*)d_in[0];
    float* out = (float*)d_out;
    dim3 grid(S_LEN / TILE_S, 32);   // (64 seq tiles, 32 batches)
    cwt_kernel<<<grid, NT>>>(x, out);
}

// round 5
// speedup vs baseline: 3.6909x; 2.7018x over previous
#include <cuda_runtime.h>

// CWT gaus1, scales {1,3,6}, x:(32,4096,64) f32 -> out:(32,3,4096,64) f32.
//
// Folded form: out_a[b,s,c] = sum_m h_a[m] * x[b, s + start_a + m, c]
//   h_a[m] = -sqrt(a)*(f_a[m-1]-f_a[m]),  f_a[i] = int_psi[floor(i/(a*step))]
// Unified window p in [0,61] relative to x[s-31]: scale6 tap m=p (all p),
// scale3 m=p-15 for p in [15,46], scale1 m=p-25 for p in [25,36].
//
// R5 (R4 fixed): coefficients are compile-time constants materialized as
// LOCAL constexpr floats inside template<int P> steps — device-legal without
// --expt-relaxed-constexpr, and guaranteed FFMA-with-immediate in SASS.
// Removes the 106 exposed coefficient-LDS stalls/thread that bound R1-R3.

#define S_LEN 4096
#define C_LEN 64
#define TILE_S 64
#define NROWS 125   // TILE_S + 61
#define NT 512
#define T 8         // seq rows per thread

// ---------------- compile-time coefficient math ----------------
__host__ __device__ constexpr double cpow2i(int n) {
    double r = 1.0;
    if (n >= 0) { for (int i = 0; i <  n; i++) r *= 2.0; }
    else        { for (int i = 0; i < -n; i++) r *= 0.5; }
    return r;
}
// exp(x) for x in [-30, 1]: range-reduce by ln2, 20-term Taylor.
__host__ __device__ constexpr double cexp(double x) {
    const double ln2 = 0.6931471805599453;
    int n = (int)(x / ln2 + (x >= 0.0 ? 0.5 : -0.5));
    double r = x - (double)n * ln2;
    double term = 1.0, sum = 1.0;
    for (int k = 1; k <= 20; k++) { term *= r / (double)k; sum += term; }
    return sum * cpow2i(n);
}
__host__ __device__ constexpr double csqrt_(double x) {
    double g = x > 1.0 ? x : 1.0;
    for (int i = 0; i < 64; i++) g = 0.5 * (g + x / g);
    return g;
}
// Euler-Maclaurin model of numpy cumsum(psi)*step for gaus1 (validated R1-R3
// at rel_err 4e-7); model error ~1e-8, constexpr-math error ~1e-15.
__host__ __device__ constexpr double ipsi_em(long j) {
    const double step = 10.0 / 1023.0;
    double u = (j >= 1023) ? 5.0 : ((double)j * step - 5.0);
    double e = cexp(-u * u);
    double v = e * (1.0 - step * u + (step * step / 12.0) * (4.0 * u * u - 2.0));
    return v / csqrt_(csqrt_(3.141592653589793 / 2.0));   // (pi/2)^(1/4)
}
__host__ __device__ constexpr float f_at(int a, int i, int L) {
    if (i < 0 || i >= L) return 0.0f;
    const double step = 10.0 / 1023.0;
    double as_ = (double)a * step;          // matches numpy a*step (f64)
    long j = (long)((double)i / as_);       // matches arange/(a*step) astype(int64)
    return (float)ipsi_em(j);
}
__host__ __device__ constexpr float hval(int a, int L, int m) {
    float fm1 = f_at(a, m - 1, L), fm = f_at(a, m, L);
    return -(float)csqrt_((double)a) * (fm1 - fm);   // f32 math like reference
}

// ---------------- template-unrolled tap steps ----------------
template<int P>
__device__ __forceinline__ void tap_step(const float (*xs)[C_LEN], int rbase, int ch,
                                         float (&win)[12],
                                         float (&A6)[T], float (&A3)[T], float (&A1)[T]) {
    if constexpr (P < 62) {
        if constexpr (P + 10 <= 68)   // prefetch row P+10 (first used at iter P+3)
            win[(P + 10) % 12] = xs[rbase + P + 10][ch];
        {
            constexpr float c6 = hval(6, 61, P);
            #pragma unroll
            for (int t = 0; t < T; t++)
                A6[t] = fmaf(win[(P + t) % 12], c6, A6[t]);
        }
        if constexpr (P >= 15 && P < 47) {
            constexpr float c3 = hval(3, 31, P - 15);
            #pragma unroll
            for (int t = 0; t < T; t++)
                A3[t] = fmaf(win[(P + t) % 12], c3, A3[t]);
        }
        if constexpr (P >= 25 && P < 37) {
            constexpr float c1 = hval(1, 11, P - 25);
            #pragma unroll
            for (int t = 0; t < T; t++)
                A1[t] = fmaf(win[(P + t) % 12], c1, A1[t]);
        }
        tap_step<P + 1>(xs, rbase, ch, win, A6, A3, A1);
    }
}

// ---------------- kernel ----------------
__global__ void __launch_bounds__(NT)
cwt_kernel(const float* __restrict__ x, float* __restrict__ out) {
    __shared__ float xs[NROWS][C_LEN];

    const int tid = threadIdx.x;
    const int b   = blockIdx.y;
    const int s0  = blockIdx.x * TILE_S;

    // ---- fill smem tile (rows s0-31 .. s0+93, zero-padded at edges) ----
    const float4* xg = (const float4*)x + (size_t)b * (S_LEN * (C_LEN / 4));
    const float4 z4 = make_float4(0.f, 0.f, 0.f, 0.f);
    #pragma unroll
    for (int k = 0; k < 4; k++) {
        int f = tid + k * NT;
        if (f < NROWS * 16) {
            int row = f >> 4, q = f & 15;
            int gs = s0 - 31 + row;
            float4 v = (gs >= 0 && gs < S_LEN) ? xg[gs * 16 + q] : z4;
            *(float4*)&xs[row][q * 4] = v;
        }
    }
    __syncthreads();

    // ---- compute: thread = 1 channel x 8 seq rows x 3 scales ----
    const int lane  = tid & 31;
    const int w     = tid >> 5;               // 16 warps
    const int sg    = w & 7;                  // seq group 0..7
    const int ch    = (w >> 3) * 32 + lane;   // channel 0..63
    const int rbase = sg * T;

    // 12-deep modular ring; rows p..p+10 live at iteration p.
    float win[12];
    #pragma unroll
    for (int r = 0; r < 10; r++) win[r] = xs[rbase + r][ch];

    float A6[T] = {0}, A3[T] = {0}, A1[T] = {0};
    tap_step<0>(xs, rbase, ch, win, A6, A3, A1);

    // ---- store: out[b, scale, s, c], scale order (1,3,6) ----
    float* og = out + (size_t)b * 3 * S_LEN * C_LEN;
    const int srow = s0 + rbase;
    #pragma unroll
    for (int t = 0; t < T; t++) {
        size_t r = (size_t)(srow + t) * C_LEN + ch;
        og[0 * (size_t)S_LEN * C_LEN + r] = A1[t];
        og[1 * (size_t)S_LEN * C_LEN + r] = A3[t];
        og[2 * (size_t)S_LEN * C_LEN + r] = A6[t];
    }
}

extern "C" void kernel_launch(void* const* d_in, const int* in_sizes, int n_in,
                              void* d_out, int out_size) {
    const float* x = (const float*)d_in[0];
    float* out = (float*)d_out;
    dim3 grid(S_LEN / TILE_S, 32);   // (64 seq tiles, 32 batches)
    cwt_kernel<<<grid, NT>>>(x, out);
}

// round 6
// speedup vs baseline: 4.0479x; 1.0967x over previous
#include <cuda_runtime.h>

// CWT gaus1, scales {1,3,6}, x:(32,4096,64) f32 -> out:(32,3,4096,64) f32.
//
// Folded form: out_a[b,s,c] = sum_m h_a[m] * x[b, s + start_a + m, c]
//   h_a[m] = -sqrt(a)*(f_a[m-1]-f_a[m]),  f_a[i] = int_psi[floor(i/(a*step))]
// Unified window p in [0,61] relative to x[s-31]: scale6 tap m=p (all p),
// scale3 m=p-15 for p in [15,46], scale1 m=p-25 for p in [25,36].
//
// R6: pack 2 channels/thread with fma.rn.f32x2 (FFMA2: 2 FMA lanes per issue
// slot) — halves FMA issue pressure vs R5's scalar FFMA-imm. Taps are
// compile-time floats bit-cast (constexpr, exact) into broadcast-packed
// 64-bit literals. TILE_S=128 cuts halo DRAM amplification to 1.48x.

#define S_LEN 4096
#define C_LEN 64
#define TILE_S 128
#define NROWS 189   // TILE_S + 61
#define NT 512
#define T 8         // seq rows per thread

typedef unsigned long long ull;

// ---------------- compile-time coefficient math ----------------
__host__ __device__ constexpr double cpow2i(int n) {
    double r = 1.0;
    if (n >= 0) { for (int i = 0; i <  n; i++) r *= 2.0; }
    else        { for (int i = 0; i < -n; i++) r *= 0.5; }
    return r;
}
__host__ __device__ constexpr double cexp(double x) {
    const double ln2 = 0.6931471805599453;
    int n = (int)(x / ln2 + (x >= 0.0 ? 0.5 : -0.5));
    double r = x - (double)n * ln2;
    double term = 1.0, sum = 1.0;
    for (int k = 1; k <= 20; k++) { term *= r / (double)k; sum += term; }
    return sum * cpow2i(n);
}
__host__ __device__ constexpr double csqrt_(double x) {
    double g = x > 1.0 ? x : 1.0;
    for (int i = 0; i < 64; i++) g = 0.5 * (g + x / g);
    return g;
}
// Euler-Maclaurin model of numpy cumsum(psi)*step for gaus1 (validated at
// rel_err 4e-7 in R1-R5).
__host__ __device__ constexpr double ipsi_em(long j) {
    const double step = 10.0 / 1023.0;
    double u = (j >= 1023) ? 5.0 : ((double)j * step - 5.0);
    double e = cexp(-u * u);
    double v = e * (1.0 - step * u + (step * step / 12.0) * (4.0 * u * u - 2.0));
    return v / csqrt_(csqrt_(3.141592653589793 / 2.0));   // (pi/2)^(1/4)
}
__host__ __device__ constexpr float f_at(int a, int i, int L) {
    if (i < 0 || i >= L) return 0.0f;
    const double step = 10.0 / 1023.0;
    double as_ = (double)a * step;          // matches numpy a*step (f64)
    long j = (long)((double)i / as_);       // matches arange/(a*step) astype(int64)
    return (float)ipsi_em(j);
}
__host__ __device__ constexpr float hval(int a, int L, int m) {
    float fm1 = f_at(a, m - 1, L), fm = f_at(a, m, L);
    return -(float)csqrt_((double)a) * (fm1 - fm);   // f32 math like reference
}
// exact constexpr float->bits (taps are normal floats, mantissa integer-exact)
__host__ __device__ constexpr unsigned int f2b(float v) {
    if (v == 0.0f) return 0u;
    unsigned int s = 0; double a = (double)v;
    if (a < 0.0) { s = 0x80000000u; a = -a; }
    int e = 0;
    while (a >= 2.0) { a *= 0.5; e++; }
    while (a < 1.0)  { a *= 2.0; e--; }
    unsigned long long m = (unsigned long long)(a * 8388608.0);  // exact
    return s | ((unsigned int)(e + 127) << 23) | ((unsigned int)m & 0x7FFFFFu);
}
__host__ __device__ constexpr ull pk(float v) {
    unsigned int b = f2b(v);
    return ((ull)b << 32) | (ull)b;
}

__device__ __forceinline__ void ffma2(ull &d, ull a, ull b) {
    asm("fma.rn.f32x2 %0, %1, %2, %0;" : "+l"(d) : "l"(a), "l"(b));
}

// ---------------- template-unrolled tap steps ----------------
template<int P>
__device__ __forceinline__ void tap_step(const float (*xs)[C_LEN], int rbase, int pr,
                                         ull (&win)[12],
                                         ull (&A6)[T], ull (&A3)[T], ull (&A1)[T]) {
    if constexpr (P < 62) {
        if constexpr (P + 10 <= 68)   // prefetch row P+10 (first used at iter P+3)
            win[(P + 10) % 12] = *(const ull*)&xs[rbase + P + 10][pr * 2];
        {
            constexpr ull c6 = pk(hval(6, 61, P));
            #pragma unroll
            for (int t = 0; t < T; t++)
                ffma2(A6[t], win[(P + t) % 12], c6);
        }
        if constexpr (P >= 15 && P < 47) {
            constexpr ull c3 = pk(hval(3, 31, P - 15));
            #pragma unroll
            for (int t = 0; t < T; t++)
                ffma2(A3[t], win[(P + t) % 12], c3);
        }
        if constexpr (P >= 25 && P < 37) {
            constexpr ull c1 = pk(hval(1, 11, P - 25));
            #pragma unroll
            for (int t = 0; t < T; t++)
                ffma2(A1[t], win[(P + t) % 12], c1);
        }
        tap_step<P + 1>(xs, rbase, pr, win, A6, A3, A1);
    }
}

// ---------------- kernel ----------------
__global__ void __launch_bounds__(NT)
cwt_kernel(const float* __restrict__ x, float* __restrict__ out) {
    __shared__ float xs[NROWS][C_LEN];

    const int tid = threadIdx.x;
    const int b   = blockIdx.y;
    const int s0  = blockIdx.x * TILE_S;

    // ---- fill smem tile (rows s0-31 .. s0+157, zero-padded at edges) ----
    const float4* xg = (const float4*)x + (size_t)b * (S_LEN * (C_LEN / 4));
    const float4 z4 = make_float4(0.f, 0.f, 0.f, 0.f);
    #pragma unroll
    for (int k = 0; k < 6; k++) {
        int f = tid + k * NT;
        if (f < NROWS * 16) {
            int row = f >> 4, q = f & 15;
            int gs = s0 - 31 + row;
            float4 v = (gs >= 0 && gs < S_LEN) ? xg[gs * 16 + q] : z4;
            *(float4*)&xs[row][q * 4] = v;
        }
    }
    __syncthreads();

    // ---- compute: thread = 2 channels x 8 seq rows x 3 scales ----
    const int pr    = tid & 31;          // channel pair 0..31
    const int sg    = tid >> 5;          // seq group 0..15
    const int rbase = sg * T;

    // 12-deep modular ring of rows (as packed channel pairs)
    ull win[12];
    #pragma unroll
    for (int r = 0; r < 10; r++)
        win[r] = *(const ull*)&xs[rbase + r][pr * 2];

    ull A6[T] = {0}, A3[T] = {0}, A1[T] = {0};
    tap_step<0>(xs, rbase, pr, win, A6, A3, A1);

    // ---- store: out[b, scale, s, c], scale order (1,3,6) ----
    ull* og = (ull*)out + (size_t)b * 3 * S_LEN * (C_LEN / 2);
    const int srow = s0 + rbase;
    #pragma unroll
    for (int t = 0; t < T; t++) {
        size_t r = (size_t)(srow + t) * (C_LEN / 2) + pr;
        og[0 * (size_t)S_LEN * (C_LEN / 2) + r] = A1[t];
        og[1 * (size_t)S_LEN * (C_LEN / 2) + r] = A3[t];
        og[2 * (size_t)S_LEN * (C_LEN / 2) + r] = A6[t];
    }
}

extern "C" void kernel_launch(void* const* d_in, const int* in_sizes, int n_in,
                              void* d_out, int out_size) {
    const float* x = (const float*)d_in[0];
    float* out = (float*)d_out;
    dim3 grid(S_LEN / TILE_S, 32);   // (32 seq tiles, 32 batches)
    cwt_kernel<<<grid, NT>>>(x, out);
}

// round 7
// speedup vs baseline: 4.2518x; 1.0504x over previous
#include <cuda_runtime.h>

// CWT gaus1, scales {1,3,6}, x:(32,4096,64) f32 -> out:(32,3,4096,64) f32.
//
// Folded form: out_a[b,s,c] = sum_m h_a[m] * x[b, s + start_a + m, c]
//   h_a[m] = -sqrt(a)*(f_a[m-1]-f_a[m]),  f_a[i] = int_psi[floor(i/(a*step))]
// Unified window p in [0,61] relative to x[s-31]: scale6 tap m=p (all p),
// scale3 m=p-15 for p in [15,46], scale1 m=p-25 for p in [25,36].
//
// R7 = R6 (fma.rn.f32x2, compile-time packed tap literals) + R5's occupancy:
// NT=256, TILE_S=64 -> 31.25 KB smem -> 3-4 blocks/SM (occ ~80%) so the
// halved FFMA2 issue demand actually converts into fma-pipe residency.

#define S_LEN 4096
#define C_LEN 64
#define TILE_S 64
#define NROWS 125   // TILE_S + 61
#define NT 256
#define T 8         // seq rows per thread

typedef unsigned long long ull;

// ---------------- compile-time coefficient math ----------------
__host__ __device__ constexpr double cpow2i(int n) {
    double r = 1.0;
    if (n >= 0) { for (int i = 0; i <  n; i++) r *= 2.0; }
    else        { for (int i = 0; i < -n; i++) r *= 0.5; }
    return r;
}
__host__ __device__ constexpr double cexp(double x) {
    const double ln2 = 0.6931471805599453;
    int n = (int)(x / ln2 + (x >= 0.0 ? 0.5 : -0.5));
    double r = x - (double)n * ln2;
    double term = 1.0, sum = 1.0;
    for (int k = 1; k <= 20; k++) { term *= r / (double)k; sum += term; }
    return sum * cpow2i(n);
}
__host__ __device__ constexpr double csqrt_(double x) {
    double g = x > 1.0 ? x : 1.0;
    for (int i = 0; i < 64; i++) g = 0.5 * (g + x / g);
    return g;
}
// Euler-Maclaurin model of numpy cumsum(psi)*step for gaus1 (validated at
// rel_err 4e-7 in R1-R6).
__host__ __device__ constexpr double ipsi_em(long j) {
    const double step = 10.0 / 1023.0;
    double u = (j >= 1023) ? 5.0 : ((double)j * step - 5.0);
    double e = cexp(-u * u);
    double v = e * (1.0 - step * u + (step * step / 12.0) * (4.0 * u * u - 2.0));
    return v / csqrt_(csqrt_(3.141592653589793 / 2.0));   // (pi/2)^(1/4)
}
__host__ __device__ constexpr float f_at(int a, int i, int L) {
    if (i < 0 || i >= L) return 0.0f;
    const double step = 10.0 / 1023.0;
    double as_ = (double)a * step;          // matches numpy a*step (f64)
    long j = (long)((double)i / as_);       // matches arange/(a*step) astype(int64)
    return (float)ipsi_em(j);
}
__host__ __device__ constexpr float hval(int a, int L, int m) {
    float fm1 = f_at(a, m - 1, L), fm = f_at(a, m, L);
    return -(float)csqrt_((double)a) * (fm1 - fm);   // f32 math like reference
}
// exact constexpr float->bits (taps are normal floats, mantissa integer-exact)
__host__ __device__ constexpr unsigned int f2b(float v) {
    if (v == 0.0f) return 0u;
    unsigned int s = 0; double a = (double)v;
    if (a < 0.0) { s = 0x80000000u; a = -a; }
    int e = 0;
    while (a >= 2.0) { a *= 0.5; e++; }
    while (a < 1.0)  { a *= 2.0; e--; }
    unsigned long long m = (unsigned long long)(a * 8388608.0);  // exact
    return s | ((unsigned int)(e + 127) << 23) | ((unsigned int)m & 0x7FFFFFu);
}
__host__ __device__ constexpr ull pk(float v) {
    unsigned int b = f2b(v);
    return ((ull)b << 32) | (ull)b;
}

__device__ __forceinline__ void ffma2(ull &d, ull a, ull b) {
    asm("fma.rn.f32x2 %0, %1, %2, %0;" : "+l"(d) : "l"(a), "l"(b));
}

// ---------------- template-unrolled tap steps ----------------
template<int P>
__device__ __forceinline__ void tap_step(const float (*xs)[C_LEN], int rbase, int pr,
                                         ull (&win)[12],
                                         ull (&A6)[T], ull (&A3)[T], ull (&A1)[T]) {
    if constexpr (P < 62) {
        if constexpr (P + 10 <= 68)   // prefetch row P+10 (first used at iter P+3)
            win[(P + 10) % 12] = *(const ull*)&xs[rbase + P + 10][pr * 2];
        {
            constexpr ull c6 = pk(hval(6, 61, P));
            #pragma unroll
            for (int t = 0; t < T; t++)
                ffma2(A6[t], win[(P + t) % 12], c6);
        }
        if constexpr (P >= 15 && P < 47) {
            constexpr ull c3 = pk(hval(3, 31, P - 15));
            #pragma unroll
            for (int t = 0; t < T; t++)
                ffma2(A3[t], win[(P + t) % 12], c3);
        }
        if constexpr (P >= 25 && P < 37) {
            constexpr ull c1 = pk(hval(1, 11, P - 25));
            #pragma unroll
            for (int t = 0; t < T; t++)
                ffma2(A1[t], win[(P + t) % 12], c1);
        }
        tap_step<P + 1>(xs, rbase, pr, win, A6, A3, A1);
    }
}

// ---------------- kernel ----------------
__global__ void __launch_bounds__(NT)
cwt_kernel(const float* __restrict__ x, float* __restrict__ out) {
    __shared__ float xs[NROWS][C_LEN];

    const int tid = threadIdx.x;
    const int b   = blockIdx.y;
    const int s0  = blockIdx.x * TILE_S;

    // ---- fill smem tile (rows s0-31 .. s0+93, zero-padded at edges) ----
    const float4* xg = (const float4*)x + (size_t)b * (S_LEN * (C_LEN / 4));
    const float4 z4 = make_float4(0.f, 0.f, 0.f, 0.f);
    #pragma unroll
    for (int k = 0; k < 8; k++) {
        int f = tid + k * NT;
        if (f < NROWS * 16) {
            int row = f >> 4, q = f & 15;
            int gs = s0 - 31 + row;
            float4 v = (gs >= 0 && gs < S_LEN) ? xg[gs * 16 + q] : z4;
            *(float4*)&xs[row][q * 4] = v;
        }
    }
    __syncthreads();

    // ---- compute: thread = 2 channels x 8 seq rows x 3 scales ----
    const int pr    = tid & 31;          // channel pair 0..31
    const int sg    = tid >> 5;          // seq group 0..7
    const int rbase = sg * T;

    // 12-deep modular ring of rows (as packed channel pairs)
    ull win[12];
    #pragma unroll
    for (int r = 0; r < 10; r++)
        win[r] = *(const ull*)&xs[rbase + r][pr * 2];

    ull A6[T] = {0}, A3[T] = {0}, A1[T] = {0};
    tap_step<0>(xs, rbase, pr, win, A6, A3, A1);

    // ---- store: out[b, scale, s, c], scale order (1,3,6) ----
    ull* og = (ull*)out + (size_t)b * 3 * S_LEN * (C_LEN / 2);
    const int srow = s0 + rbase;
    #pragma unroll
    for (int t = 0; t < T; t++) {
        size_t r = (size_t)(srow + t) * (C_LEN / 2) + pr;
        og[0 * (size_t)S_LEN * (C_LEN / 2) + r] = A1[t];
        og[1 * (size_t)S_LEN * (C_LEN / 2) + r] = A3[t];
        og[2 * (size_t)S_LEN * (C_LEN / 2) + r] = A6[t];
    }
}

extern "C" void kernel_launch(void* const* d_in, const int* in_sizes, int n_in,
                              void* d_out, int out_size) {
    const float* x = (const float*)d_in[0];
    float* out = (float*)d_out;
    dim3 grid(S_LEN / TILE_S, 32);   // (64 seq tiles, 32 batches)
    cwt_kernel<<<grid, NT>>>(x, out);
}